// round 3
// baseline (speedup 1.0000x reference)
#include <cuda_runtime.h>
#include <cuda_bf16.h>

#define NN 100000
#define NE 3200000
#define DF 512
#define HID 16
#define NC 7

// gemm1 tiling
#define TR 256            // rows per block
#define KC 32             // k-chunk
#define XS_STRIDE 260     // padded row-stride for transposed x tile (16B-aligned float4, conflict-free)

// ---------------- scratch (no allocations allowed) ----------------
__device__ float g_deg[NN];
__device__ float g_dinv[NN];
__device__ float g_w[NE];                        // per-edge weight, computed in scat1, reused in scat2
__device__ __align__(16) float g_h1[NN * HID];   // x @ W1
__device__ __align__(16) float g_m1[NN * HID];   // aggregated layer1
__device__ __align__(16) float g_t2[NN * 8];     // relu(m1+b1) @ W2, padded to 8
__device__ __align__(16) float g_m2[NN * 8];     // aggregated layer2, padded

// 128-bit global float reduction (sm_90+)
__device__ __forceinline__ void red_add_v4(float* p, float4 v) {
    asm volatile(
        "{\n\t"
        ".reg .u64 pg;\n\t"
        "cvta.to.global.u64 pg, %0;\n\t"
        "red.global.add.v4.f32 [pg], {%1,%2,%3,%4};\n\t"
        "}"
        :: "l"(p), "f"(v.x), "f"(v.y), "f"(v.z), "f"(v.w)
        : "memory");
}

__device__ __forceinline__ void ffma2(unsigned long long& acc,
                                      unsigned long long a, unsigned long long b) {
    asm("fma.rn.f32x2 %0, %1, %2, %0;" : "+l"(acc) : "l"(a), "l"(b));
}

// ---------------- K0: init accumulators ----------------
__global__ void k_init() {
    int i = blockIdx.x * blockDim.x + threadIdx.x;
    if (i < NN) g_deg[i] = 1.0f;          // self-loop contributes 1 to degree
    if (i < NN * HID) g_m1[i] = 0.0f;
    if (i < NN * 8) g_m2[i] = 0.0f;
}

// ---------------- K1: in-degree ----------------
__global__ void k_deg(const int* __restrict__ ei) {
    int e = blockIdx.x * blockDim.x + threadIdx.x;
    if (e < NE) atomicAdd(&g_deg[ei[NE + e]], 1.0f);
}

// ---------------- K2: dinv ----------------
__global__ void k_dinv() {
    int i = blockIdx.x * blockDim.x + threadIdx.x;
    if (i < NN) g_dinv[i] = rsqrtf(g_deg[i]);   // deg >= 1 always
}

// ---------------- K3: h1 = x @ W1 via packed f32x2 FMA ----------------
// 256 threads; tile = 256 rows x 16 cols. Thread t: rq = t>>2 (4 rows), cg = t&3 (4 cols).
// x staged TRANSPOSED in smem: xs[k][row]; W staged duplicated as {w,w} float2.
__global__ void k_gemm1(const float* __restrict__ x, const float* __restrict__ W1) {
    __shared__ __align__(16) float xs[KC * XS_STRIDE];   // 33.3 KB
    __shared__ __align__(16) float2 Wd[KC][HID];         // 4 KB, duplicated W chunk

    int t = threadIdx.x;
    int row0 = blockIdx.x * TR;
    int rq = t >> 2;          // 0..63 -> rows rq*4 .. rq*4+3
    int cg = t & 3;           // 0..3  -> cols cg*4 .. cg*4+3

    unsigned long long acc[2][4];
    #pragma unroll
    for (int p = 0; p < 2; p++)
        #pragma unroll
        for (int c = 0; c < 4; c++) acc[p][c] = 0ull;

    for (int kc = 0; kc < DF; kc += KC) {
        __syncthreads();
        // stage W chunk, duplicated into both f32x2 halves
        for (int i = t; i < KC * HID; i += 256) {
            int k = i >> 4, c = i & 15;
            float w = W1[(kc + k) * HID + c];
            Wd[k][c] = make_float2(w, w);
        }
        // stage x chunk transposed: coalesced float4 loads, scalar transposed stores
        #pragma unroll
        for (int i = 0; i < 8; i++) {
            int linear = t + 256 * i;
            int row = linear >> 3;        // 0..255
            int kq = linear & 7;          // 0..7 (float4 groups of k)
            int grow = row0 + row;
            float4 v = make_float4(0.f, 0.f, 0.f, 0.f);
            if (grow < NN) v = *(const float4*)&x[grow * DF + kc + kq * 4];
            xs[(kq * 4 + 0) * XS_STRIDE + row] = v.x;
            xs[(kq * 4 + 1) * XS_STRIDE + row] = v.y;
            xs[(kq * 4 + 2) * XS_STRIDE + row] = v.z;
            xs[(kq * 4 + 3) * XS_STRIDE + row] = v.w;
        }
        __syncthreads();
        #pragma unroll
        for (int k = 0; k < KC; k++) {
            // 4 row-values = 2 row-pairs in one 128-bit load
            ulonglong2 xp = *(const ulonglong2*)&xs[k * XS_STRIDE + rq * 4];
            // 4 duplicated W cols in two 128-bit loads
            ulonglong2 wa = *(const ulonglong2*)&Wd[k][cg * 4];
            ulonglong2 wb = *(const ulonglong2*)&Wd[k][cg * 4 + 2];
            ffma2(acc[0][0], xp.x, wa.x);
            ffma2(acc[0][1], xp.x, wa.y);
            ffma2(acc[0][2], xp.x, wb.x);
            ffma2(acc[0][3], xp.x, wb.y);
            ffma2(acc[1][0], xp.y, wa.x);
            ffma2(acc[1][1], xp.y, wa.y);
            ffma2(acc[1][2], xp.y, wb.x);
            ffma2(acc[1][3], xp.y, wb.y);
        }
    }

    #pragma unroll
    for (int p = 0; p < 2; p++) {
        int r = row0 + rq * 4 + p * 2;
        #pragma unroll
        for (int c = 0; c < 4; c++) {
            float lo, hi;
            asm("mov.b64 {%0,%1}, %2;" : "=f"(lo), "=f"(hi) : "l"(acc[p][c]));
            if (r < NN)     g_h1[r * HID + cg * 4 + c] = lo;
            if (r + 1 < NN) g_h1[(r + 1) * HID + cg * 4 + c] = hi;
        }
    }
}

// ---------------- K4: layer-1 scatter (1 thread/edge, 4x v4 red, stores w) ----
__global__ void k_scat1(const int* __restrict__ ei) {
    int e = blockIdx.x * blockDim.x + threadIdx.x;
    if (e >= NE) return;
    int src = ei[e];
    int dst = ei[NE + e];
    float w = g_dinv[src] * g_dinv[dst];
    g_w[e] = w;
    const float4* hp = (const float4*)&g_h1[src * HID];
    float4 a = hp[0], b = hp[1], c = hp[2], d = hp[3];
    a.x *= w; a.y *= w; a.z *= w; a.w *= w;
    b.x *= w; b.y *= w; b.z *= w; b.w *= w;
    c.x *= w; c.y *= w; c.z *= w; c.w *= w;
    d.x *= w; d.y *= w; d.z *= w; d.w *= w;
    float* mp = &g_m1[dst * HID];
    red_add_v4(mp + 0,  a);
    red_add_v4(mp + 4,  b);
    red_add_v4(mp + 8,  c);
    red_add_v4(mp + 12, d);
}

// ---------------- K5: h2 = relu(m1 + selfloop + b1); t2 = h2 @ W2 ----------------
__global__ void k_layer2(const float* __restrict__ b1, const float* __restrict__ W2) {
    __shared__ float W2s[HID][8];
    __shared__ float b1s[HID];
    int t = threadIdx.x;
    if (t < HID * NC) W2s[t / NC][t % NC] = W2[t];
    if (t < HID) { W2s[t][7] = 0.0f; b1s[t] = b1[t]; }
    __syncthreads();

    int n = blockIdx.x * blockDim.x + t;
    if (n >= NN) return;
    float dv = g_dinv[n];
    float d2 = dv * dv;

    float h[HID];
    #pragma unroll
    for (int j = 0; j < 4; j++) {
        float4 mv = ((const float4*)g_m1)[n * 4 + j];
        float4 hv = ((const float4*)g_h1)[n * 4 + j];
        h[4 * j + 0] = fmaxf(mv.x + hv.x * d2 + b1s[4 * j + 0], 0.f);
        h[4 * j + 1] = fmaxf(mv.y + hv.y * d2 + b1s[4 * j + 1], 0.f);
        h[4 * j + 2] = fmaxf(mv.z + hv.z * d2 + b1s[4 * j + 2], 0.f);
        h[4 * j + 3] = fmaxf(mv.w + hv.w * d2 + b1s[4 * j + 3], 0.f);
    }

    float o[8];
    #pragma unroll
    for (int c = 0; c < 8; c++) o[c] = 0.f;
    #pragma unroll
    for (int k = 0; k < HID; k++) {
        #pragma unroll
        for (int c = 0; c < 8; c++)
            o[c] += h[k] * W2s[k][c];    // col 7 stays 0
    }
    ((float4*)g_t2)[n * 2 + 0] = make_float4(o[0], o[1], o[2], o[3]);
    ((float4*)g_t2)[n * 2 + 1] = make_float4(o[4], o[5], o[6], o[7]);
}

// ---------------- K6: layer-2 scatter (1 thread/edge, reuses w) ----------------
__global__ void k_scat2(const int* __restrict__ ei) {
    int e = blockIdx.x * blockDim.x + threadIdx.x;
    if (e >= NE) return;
    int src = ei[e];
    int dst = ei[NE + e];
    float w = g_w[e];
    const float4* tp = (const float4*)&g_t2[src * 8];
    float4 a = tp[0], b = tp[1];
    a.x *= w; a.y *= w; a.z *= w; a.w *= w;
    b.x *= w; b.y *= w; b.z *= w; b.w *= w;
    float* mp = &g_m2[dst * 8];
    red_add_v4(mp + 0, a);
    red_add_v4(mp + 4, b);
}

// ---------------- K7: finalize: + selfloop + b2, log_softmax ----------------
__global__ void k_final(const float* __restrict__ b2, float* __restrict__ out) {
    int n = blockIdx.x * blockDim.x + threadIdx.x;
    if (n >= NN) return;
    float dv = g_dinv[n];
    float d2 = dv * dv;

    float4 m0 = ((const float4*)g_m2)[n * 2 + 0];
    float4 m1v = ((const float4*)g_m2)[n * 2 + 1];
    float4 t0 = ((const float4*)g_t2)[n * 2 + 0];
    float4 t1 = ((const float4*)g_t2)[n * 2 + 1];

    float l[NC];
    l[0] = m0.x + t0.x * d2 + b2[0];
    l[1] = m0.y + t0.y * d2 + b2[1];
    l[2] = m0.z + t0.z * d2 + b2[2];
    l[3] = m0.w + t0.w * d2 + b2[3];
    l[4] = m1v.x + t1.x * d2 + b2[4];
    l[5] = m1v.y + t1.y * d2 + b2[5];
    l[6] = m1v.z + t1.z * d2 + b2[6];

    float mx = l[0];
    #pragma unroll
    for (int c = 1; c < NC; c++) mx = fmaxf(mx, l[c]);
    float s = 0.f;
    #pragma unroll
    for (int c = 0; c < NC; c++) s += expf(l[c] - mx);
    float lse = mx + logf(s);
    #pragma unroll
    for (int c = 0; c < NC; c++) out[n * NC + c] = l[c] - lse;
}

// ---------------- launch ----------------
extern "C" void kernel_launch(void* const* d_in, const int* in_sizes, int n_in,
                              void* d_out, int out_size) {
    const float* x   = (const float*)d_in[0];
    const int*   ei  = (const int*)d_in[1];
    const float* W1  = (const float*)d_in[2];
    const float* b1  = (const float*)d_in[3];
    const float* W2  = (const float*)d_in[4];
    const float* b2  = (const float*)d_in[5];
    float*       out = (float*)d_out;

    k_init<<<(NN * HID + 255) / 256, 256>>>();
    k_deg<<<(NE + 255) / 256, 256>>>(ei);
    k_dinv<<<(NN + 255) / 256, 256>>>();
    k_gemm1<<<(NN + TR - 1) / TR, 256>>>(x, W1);
    k_scat1<<<(NE + 255) / 256, 256>>>(ei);
    k_layer2<<<(NN + 255) / 256, 256>>>(b1, W2);
    k_scat2<<<(NE + 255) / 256, 256>>>(ei);
    k_final<<<(NN + 255) / 256, 256>>>(b2, out);
}

// round 4
// speedup vs baseline: 1.0141x; 1.0141x over previous
#include <cuda_runtime.h>
#include <cuda_bf16.h>

#define NN 100000
#define NE 3200000
#define DF 512
#define HID 16
#define NC 7

// gemm1 tiling: 128 rows x 16 cols per 256-thread block; thread = 2 rows x 4 cols
#define TRB 128
#define KC  32
#define XST 132   // padded transposed-x row stride (floats)

// ---------------- scratch (no allocations allowed) ----------------
__device__ float g_deg[NN];
__device__ float g_dinv[NN];
__device__ float g_w[NE];                        // per-edge weight (scat1 -> scat2)
__device__ __align__(16) float g_h1[NN * HID];   // x @ W1
__device__ __align__(16) float g_m1[NN * HID];   // aggregated layer1
__device__ __align__(16) float g_t2[NN * 8];     // relu(m1+b1) @ W2, padded to 8
__device__ __align__(16) float g_m2[NN * 8];     // aggregated layer2, padded

// 128-bit global float reduction (sm_90+)
__device__ __forceinline__ void red_add_v4(float* p, float4 v) {
    asm volatile(
        "{\n\t"
        ".reg .u64 pg;\n\t"
        "cvta.to.global.u64 pg, %0;\n\t"
        "red.global.add.v4.f32 [pg], {%1,%2,%3,%4};\n\t"
        "}"
        :: "l"(p), "f"(v.x), "f"(v.y), "f"(v.z), "f"(v.w)
        : "memory");
}

__device__ __forceinline__ void ffma2(unsigned long long& acc,
                                      unsigned long long a, unsigned long long b) {
    asm("fma.rn.f32x2 %0, %1, %2, %0;" : "+l"(acc) : "l"(a), "l"(b));
}

// ---------------- K0: init accumulators ----------------
__global__ void k_init() {
    int i = blockIdx.x * blockDim.x + threadIdx.x;
    if (i < NN) g_deg[i] = 1.0f;          // self-loop contributes 1 to degree
    if (i < NN * HID) g_m1[i] = 0.0f;
    if (i < NN * 8) g_m2[i] = 0.0f;
}

// ---------------- K1: in-degree ----------------
__global__ void k_deg(const int* __restrict__ ei) {
    int e = blockIdx.x * blockDim.x + threadIdx.x;
    if (e < NE) atomicAdd(&g_deg[ei[NE + e]], 1.0f);
}

// ---------------- K2: dinv ----------------
__global__ void k_dinv() {
    int i = blockIdx.x * blockDim.x + threadIdx.x;
    if (i < NN) g_dinv[i] = rsqrtf(g_deg[i]);   // deg >= 1 always
}

// ---------------- K3: h1 = x @ W1, f32x2, 2 rows x 4 cols per thread ----------
__global__ void k_gemm1(const float* __restrict__ x, const float* __restrict__ W1) {
    __shared__ __align__(16) float  xs[KC * XST];   // transposed x tile, 16.9 KB
    __shared__ __align__(16) float2 Wd[KC][HID];    // duplicated W chunk, 4 KB

    int t = threadIdx.x;
    int rq = t >> 2;          // 0..63 -> row pair rq
    int cg = t & 3;           // 0..3  -> cols cg*4..cg*4+3
    int row0 = blockIdx.x * TRB;

    unsigned long long acc0 = 0ull, acc1 = 0ull, acc2 = 0ull, acc3 = 0ull;

    for (int kc = 0; kc < DF; kc += KC) {
        __syncthreads();
        // stage W chunk, duplicated {w,w}
        #pragma unroll
        for (int i = t; i < KC * HID; i += 256) {
            int k = i >> 4, c = i & 15;
            float w = W1[(kc + k) * HID + c];
            Wd[k][c] = make_float2(w, w);
        }
        // stage x chunk transposed (coalesced LDG.128, scalar transposed STS)
        #pragma unroll
        for (int i = 0; i < 2; i++) {
            int linear = t + 256 * i;     // 0..511 -> 512 float4 = 128 rows x 32 k
            int row = linear >> 3;        // 0..127... wait 512>>3 = 64
            // 128 rows x 8 f4 per row = 1024 f4 total -> need 4 iterations
            (void)row;
        }
        #pragma unroll
        for (int i = 0; i < 4; i++) {
            int linear = t + 256 * i;     // 0..1023
            int row = linear >> 3;        // 0..127
            int kq = linear & 7;          // f4 group within 32-k chunk
            int grow = row0 + row;
            float4 v = make_float4(0.f, 0.f, 0.f, 0.f);
            if (grow < NN) v = *(const float4*)&x[grow * DF + kc + kq * 4];
            xs[(kq * 4 + 0) * XST + row] = v.x;
            xs[(kq * 4 + 1) * XST + row] = v.y;
            xs[(kq * 4 + 2) * XST + row] = v.z;
            xs[(kq * 4 + 3) * XST + row] = v.w;
        }
        __syncthreads();
        #pragma unroll
        for (int k = 0; k < KC; k++) {
            unsigned long long xp = *(const unsigned long long*)&xs[k * XST + rq * 2];
            ulonglong2 wa = *(const ulonglong2*)&Wd[k][cg * 4];
            ulonglong2 wb = *(const ulonglong2*)&Wd[k][cg * 4 + 2];
            ffma2(acc0, xp, wa.x);
            ffma2(acc1, xp, wa.y);
            ffma2(acc2, xp, wb.x);
            ffma2(acc3, xp, wb.y);
        }
    }

    float l0, h0, l1, h1v, l2, h2, l3, h3;
    asm("mov.b64 {%0,%1}, %2;" : "=f"(l0), "=f"(h0) : "l"(acc0));
    asm("mov.b64 {%0,%1}, %2;" : "=f"(l1), "=f"(h1v) : "l"(acc1));
    asm("mov.b64 {%0,%1}, %2;" : "=f"(l2), "=f"(h2) : "l"(acc2));
    asm("mov.b64 {%0,%1}, %2;" : "=f"(l3), "=f"(h3) : "l"(acc3));
    int r = row0 + rq * 2;
    if (r < NN)
        *(float4*)&g_h1[r * HID + cg * 4] = make_float4(l0, l1, l2, l3);
    if (r + 1 < NN)
        *(float4*)&g_h1[(r + 1) * HID + cg * 4] = make_float4(h0, h1v, h2, h3);
}

// ---------------- K4: layer-1 scatter (4 threads/edge) + w cache -------------
__global__ void k_scat1(const int* __restrict__ ei) {
    int t = blockIdx.x * blockDim.x + threadIdx.x;
    int e = t >> 2, sub = t & 3;
    if (e >= NE) return;
    int src = ei[e];
    int dst = ei[NE + e];
    float w = g_dinv[src] * g_dinv[dst];   // coalesced-duplicate across subs (same addr)
    if (sub == 0) g_w[e] = w;
    float4 h = ((const float4*)g_h1)[src * 4 + sub];
    h.x *= w; h.y *= w; h.z *= w; h.w *= w;
    red_add_v4(&g_m1[dst * HID + sub * 4], h);
}

// ---------------- K5: h2 = relu(m1 + selfloop + b1); t2 = h2 @ W2 ------------
__global__ void k_layer2(const float* __restrict__ b1, const float* __restrict__ W2) {
    __shared__ float W2s[HID][8];
    __shared__ float b1s[HID];
    int t = threadIdx.x;
    if (t < HID * NC) W2s[t / NC][t % NC] = W2[t];
    if (t < HID) { W2s[t][7] = 0.0f; b1s[t] = b1[t]; }
    __syncthreads();

    int n = blockIdx.x * blockDim.x + t;
    if (n >= NN) return;
    float dv = g_dinv[n];
    float d2 = dv * dv;

    float h[HID];
    #pragma unroll
    for (int j = 0; j < 4; j++) {
        float4 mv = ((const float4*)g_m1)[n * 4 + j];
        float4 hv = ((const float4*)g_h1)[n * 4 + j];
        h[4 * j + 0] = fmaxf(mv.x + hv.x * d2 + b1s[4 * j + 0], 0.f);
        h[4 * j + 1] = fmaxf(mv.y + hv.y * d2 + b1s[4 * j + 1], 0.f);
        h[4 * j + 2] = fmaxf(mv.z + hv.z * d2 + b1s[4 * j + 2], 0.f);
        h[4 * j + 3] = fmaxf(mv.w + hv.w * d2 + b1s[4 * j + 3], 0.f);
    }

    float o[8];
    #pragma unroll
    for (int c = 0; c < 8; c++) o[c] = 0.f;
    #pragma unroll
    for (int k = 0; k < HID; k++) {
        #pragma unroll
        for (int c = 0; c < 8; c++)
            o[c] += h[k] * W2s[k][c];    // col 7 stays 0
    }
    ((float4*)g_t2)[n * 2 + 0] = make_float4(o[0], o[1], o[2], o[3]);
    ((float4*)g_t2)[n * 2 + 1] = make_float4(o[4], o[5], o[6], o[7]);
}

// ---------------- K6: layer-2 scatter (2 threads/edge, reuses w) -------------
__global__ void k_scat2(const int* __restrict__ ei) {
    int t = blockIdx.x * blockDim.x + threadIdx.x;
    int e = t >> 1, sub = t & 1;
    if (e >= NE) return;
    int src = ei[e];
    int dst = ei[NE + e];
    float w = g_w[e];
    float4 v = ((const float4*)g_t2)[src * 2 + sub];
    v.x *= w; v.y *= w; v.z *= w; v.w *= w;
    red_add_v4(&g_m2[dst * 8 + sub * 4], v);
}

// ---------------- K7: finalize: + selfloop + b2, log_softmax -----------------
__global__ void k_final(const float* __restrict__ b2, float* __restrict__ out) {
    int n = blockIdx.x * blockDim.x + threadIdx.x;
    if (n >= NN) return;
    float dv = g_dinv[n];
    float d2 = dv * dv;

    float4 m0 = ((const float4*)g_m2)[n * 2 + 0];
    float4 m1v = ((const float4*)g_m2)[n * 2 + 1];
    float4 t0 = ((const float4*)g_t2)[n * 2 + 0];
    float4 t1 = ((const float4*)g_t2)[n * 2 + 1];

    float l[NC];
    l[0] = m0.x + t0.x * d2 + b2[0];
    l[1] = m0.y + t0.y * d2 + b2[1];
    l[2] = m0.z + t0.z * d2 + b2[2];
    l[3] = m0.w + t0.w * d2 + b2[3];
    l[4] = m1v.x + t1.x * d2 + b2[4];
    l[5] = m1v.y + t1.y * d2 + b2[5];
    l[6] = m1v.z + t1.z * d2 + b2[6];

    float mx = l[0];
    #pragma unroll
    for (int c = 1; c < NC; c++) mx = fmaxf(mx, l[c]);
    float s = 0.f;
    #pragma unroll
    for (int c = 0; c < NC; c++) s += expf(l[c] - mx);
    float lse = mx + logf(s);
    #pragma unroll
    for (int c = 0; c < NC; c++) out[n * NC + c] = l[c] - lse;
}

// ---------------- launch ----------------
extern "C" void kernel_launch(void* const* d_in, const int* in_sizes, int n_in,
                              void* d_out, int out_size) {
    const float* x   = (const float*)d_in[0];
    const int*   ei  = (const int*)d_in[1];
    const float* W1  = (const float*)d_in[2];
    const float* b1  = (const float*)d_in[3];
    const float* W2  = (const float*)d_in[4];
    const float* b2  = (const float*)d_in[5];
    float*       out = (float*)d_out;

    k_init<<<(NN * HID + 255) / 256, 256>>>();
    k_deg<<<(NE + 255) / 256, 256>>>(ei);
    k_dinv<<<(NN + 255) / 256, 256>>>();
    k_gemm1<<<(NN + TRB - 1) / TRB, 256>>>(x, W1);
    k_scat1<<<(NE * 4 + 255) / 256, 256>>>(ei);
    k_layer2<<<(NN + 255) / 256, 256>>>(b1, W2);
    k_scat2<<<(NE * 2 + 255) / 256, 256>>>(ei);
    k_final<<<(NN + 255) / 256, 256>>>(b2, out);
}

// round 5
// speedup vs baseline: 1.4058x; 1.3862x over previous
#include <cuda_runtime.h>
#include <cuda_bf16.h>

#define NN 100000
#define NE 3200000
#define DF 512
#define HID 16
#define NC 7

// gemm1: 512 rows x 16 cols x 128-k-slice per 256-thread block; thread = 2 rows x 16 cols
#define GROWS 512
#define GKS   128          // k-slice per block (split-K = 4)
#define GKC   16           // k per staged chunk
#define GXST  17           // padded xs row stride (floats)

// ---------------- scratch (no allocations allowed) ----------------
__device__ float g_deg[NN];
__device__ float g_dinv[NN];
__device__ float g_w[NE];                        // per-edge weight (scat1 -> scat2)
__device__ __align__(16) float g_h1[NN * HID];   // x @ W1 (accumulated via red)
__device__ __align__(16) float g_m1[NN * HID];   // aggregated layer1
__device__ __align__(16) float g_t2[NN * 8];     // relu(m1+b1) @ W2, padded to 8
__device__ __align__(16) float g_m2[NN * 8];     // aggregated layer2, padded

// 128-bit global float reduction (sm_90+)
__device__ __forceinline__ void red_add_v4(float* p, float4 v) {
    asm volatile(
        "{\n\t"
        ".reg .u64 pg;\n\t"
        "cvta.to.global.u64 pg, %0;\n\t"
        "red.global.add.v4.f32 [pg], {%1,%2,%3,%4};\n\t"
        "}"
        :: "l"(p), "f"(v.x), "f"(v.y), "f"(v.z), "f"(v.w)
        : "memory");
}

__device__ __forceinline__ void ffma2(unsigned long long& acc,
                                      unsigned long long a, unsigned long long b) {
    asm("fma.rn.f32x2 %0, %1, %2, %0;" : "+l"(acc) : "l"(a), "l"(b));
}

// ---------------- K0: init accumulators ----------------
__global__ void k_init() {
    int i = blockIdx.x * blockDim.x + threadIdx.x;
    if (i < NN) g_deg[i] = 1.0f;          // self-loop contributes 1 to degree
    if (i < NN * HID) { g_m1[i] = 0.0f; g_h1[i] = 0.0f; }
    if (i < NN * 8) g_m2[i] = 0.0f;
}

// ---------------- K1: in-degree ----------------
__global__ void k_deg(const int* __restrict__ ei) {
    int e = blockIdx.x * blockDim.x + threadIdx.x;
    if (e < NE) atomicAdd(&g_deg[ei[NE + e]], 1.0f);
}

// ---------------- K2: dinv ----------------
__global__ void k_dinv() {
    int i = blockIdx.x * blockDim.x + threadIdx.x;
    if (i < NN) g_dinv[i] = rsqrtf(g_deg[i]);   // deg >= 1 always
}

// ---------------- K3: h1 += x @ W1 (split-K, col-pair f32x2) ----------------
__global__ __launch_bounds__(256) void k_gemm1(const float* __restrict__ x,
                                               const float* __restrict__ W1) {
    __shared__ __align__(16) float  xs[GROWS * GXST];   // 34.8 KB
    __shared__ __align__(8)  float2 Wp[GKS][8];         // 8 KB (col pairs)

    int t = threadIdx.x;
    int rb = blockIdx.x >> 2;
    int ks = (blockIdx.x & 3) * GKS;
    int row0 = rb * GROWS;

    // stage W slice as col-pairs (coalesced float2 loads)
    const float2* W2p = (const float2*)W1;
    #pragma unroll
    for (int i = t; i < GKS * 8; i += 256) {
        int k = i >> 3, c = i & 7;
        Wp[k][c] = W2p[(ks + k) * 8 + c];
    }

    unsigned long long acc[2][8];
    #pragma unroll
    for (int p = 0; p < 2; p++)
        #pragma unroll
        for (int c = 0; c < 8; c++) acc[p][c] = 0ull;

    for (int ch = 0; ch < GKS / GKC; ch++) {
        __syncthreads();
        // stage x chunk: 512 rows x 16 k, row-major padded
        #pragma unroll
        for (int i = 0; i < 8; i++) {
            int lin = t + 256 * i;
            int row = lin >> 2, j = lin & 3;
            int grow = row0 + row;
            float4 v = make_float4(0.f, 0.f, 0.f, 0.f);
            if (grow < NN) v = *(const float4*)&x[grow * DF + ks + ch * GKC + j * 4];
            float* p = &xs[row * GXST + j * 4];
            p[0] = v.x; p[1] = v.y; p[2] = v.z; p[3] = v.w;
        }
        __syncthreads();
        #pragma unroll
        for (int kk = 0; kk < GKC; kk++) {
            int kL = ch * GKC + kk;
            float xa = xs[t * GXST + kk];
            float xb = xs[(t + 256) * GXST + kk];
            unsigned long long xad, xbd;
            asm("mov.b64 %0, {%1,%1};" : "=l"(xad) : "f"(xa));
            asm("mov.b64 %0, {%1,%1};" : "=l"(xbd) : "f"(xb));
            #pragma unroll
            for (int c = 0; c < 8; c++) {
                unsigned long long w = *(const unsigned long long*)&Wp[kL][c];
                ffma2(acc[0][c], xad, w);
                ffma2(acc[1][c], xbd, w);
            }
        }
    }

    #pragma unroll
    for (int p = 0; p < 2; p++) {
        int r = row0 + t + p * 256;
        if (r < NN) {
            float f[16];
            #pragma unroll
            for (int c = 0; c < 8; c++)
                asm("mov.b64 {%0,%1}, %2;" : "=f"(f[2 * c]), "=f"(f[2 * c + 1]) : "l"(acc[p][c]));
            red_add_v4(&g_h1[r * HID + 0],  make_float4(f[0],  f[1],  f[2],  f[3]));
            red_add_v4(&g_h1[r * HID + 4],  make_float4(f[4],  f[5],  f[6],  f[7]));
            red_add_v4(&g_h1[r * HID + 8],  make_float4(f[8],  f[9],  f[10], f[11]));
            red_add_v4(&g_h1[r * HID + 12], make_float4(f[12], f[13], f[14], f[15]));
        }
    }
}

// ---------------- K4: layer-1 scatter (4 threads/edge) + w cache -------------
__global__ void k_scat1(const int* __restrict__ ei) {
    int t = blockIdx.x * blockDim.x + threadIdx.x;
    int e = t >> 2, sub = t & 3;
    if (e >= NE) return;
    int src = ei[e];
    int dst = ei[NE + e];
    float w = g_dinv[src] * g_dinv[dst];
    if (sub == 0) g_w[e] = w;
    float4 h = ((const float4*)g_h1)[src * 4 + sub];
    h.x *= w; h.y *= w; h.z *= w; h.w *= w;
    red_add_v4(&g_m1[dst * HID + sub * 4], h);
}

// ---------------- K5: h2 = relu(m1 + selfloop + b1); t2 = h2 @ W2 ------------
__global__ void k_layer2(const float* __restrict__ b1, const float* __restrict__ W2) {
    __shared__ float W2s[HID][8];
    __shared__ float b1s[HID];
    int t = threadIdx.x;
    if (t < HID * NC) W2s[t / NC][t % NC] = W2[t];
    if (t < HID) { W2s[t][7] = 0.0f; b1s[t] = b1[t]; }
    __syncthreads();

    int n = blockIdx.x * blockDim.x + t;
    if (n >= NN) return;
    float dv = g_dinv[n];
    float d2 = dv * dv;

    float h[HID];
    #pragma unroll
    for (int j = 0; j < 4; j++) {
        float4 mv = ((const float4*)g_m1)[n * 4 + j];
        float4 hv = ((const float4*)g_h1)[n * 4 + j];
        h[4 * j + 0] = fmaxf(mv.x + hv.x * d2 + b1s[4 * j + 0], 0.f);
        h[4 * j + 1] = fmaxf(mv.y + hv.y * d2 + b1s[4 * j + 1], 0.f);
        h[4 * j + 2] = fmaxf(mv.z + hv.z * d2 + b1s[4 * j + 2], 0.f);
        h[4 * j + 3] = fmaxf(mv.w + hv.w * d2 + b1s[4 * j + 3], 0.f);
    }

    float o[8];
    #pragma unroll
    for (int c = 0; c < 8; c++) o[c] = 0.f;
    #pragma unroll
    for (int k = 0; k < HID; k++) {
        #pragma unroll
        for (int c = 0; c < 8; c++)
            o[c] += h[k] * W2s[k][c];    // col 7 stays 0
    }
    ((float4*)g_t2)[n * 2 + 0] = make_float4(o[0], o[1], o[2], o[3]);
    ((float4*)g_t2)[n * 2 + 1] = make_float4(o[4], o[5], o[6], o[7]);
}

// ---------------- K6: layer-2 scatter (2 threads/edge, reuses w) -------------
__global__ void k_scat2(const int* __restrict__ ei) {
    int t = blockIdx.x * blockDim.x + threadIdx.x;
    int e = t >> 1, sub = t & 1;
    if (e >= NE) return;
    int src = ei[e];
    int dst = ei[NE + e];
    float w = g_w[e];
    float4 v = ((const float4*)g_t2)[src * 2 + sub];
    v.x *= w; v.y *= w; v.z *= w; v.w *= w;
    red_add_v4(&g_m2[dst * 8 + sub * 4], v);
}

// ---------------- K7: finalize: + selfloop + b2, log_softmax -----------------
__global__ void k_final(const float* __restrict__ b2, float* __restrict__ out) {
    int n = blockIdx.x * blockDim.x + threadIdx.x;
    if (n >= NN) return;
    float dv = g_dinv[n];
    float d2 = dv * dv;

    float4 m0 = ((const float4*)g_m2)[n * 2 + 0];
    float4 m1v = ((const float4*)g_m2)[n * 2 + 1];
    float4 t0 = ((const float4*)g_t2)[n * 2 + 0];
    float4 t1 = ((const float4*)g_t2)[n * 2 + 1];

    float l[NC];
    l[0] = m0.x + t0.x * d2 + b2[0];
    l[1] = m0.y + t0.y * d2 + b2[1];
    l[2] = m0.z + t0.z * d2 + b2[2];
    l[3] = m0.w + t0.w * d2 + b2[3];
    l[4] = m1v.x + t1.x * d2 + b2[4];
    l[5] = m1v.y + t1.y * d2 + b2[5];
    l[6] = m1v.z + t1.z * d2 + b2[6];

    float mx = l[0];
    #pragma unroll
    for (int c = 1; c < NC; c++) mx = fmaxf(mx, l[c]);
    float s = 0.f;
    #pragma unroll
    for (int c = 0; c < NC; c++) s += expf(l[c] - mx);
    float lse = mx + logf(s);
    #pragma unroll
    for (int c = 0; c < NC; c++) out[n * NC + c] = l[c] - lse;
}

// ---------------- launch ----------------
extern "C" void kernel_launch(void* const* d_in, const int* in_sizes, int n_in,
                              void* d_out, int out_size) {
    const float* x   = (const float*)d_in[0];
    const int*   ei  = (const int*)d_in[1];
    const float* W1  = (const float*)d_in[2];
    const float* b1  = (const float*)d_in[3];
    const float* W2  = (const float*)d_in[4];
    const float* b2  = (const float*)d_in[5];
    float*       out = (float*)d_out;

    int gblocks = ((NN + GROWS - 1) / GROWS) * 4;   // 196 * 4 = 784

    k_init<<<(NN * HID + 255) / 256, 256>>>();
    k_deg<<<(NE + 255) / 256, 256>>>(ei);
    k_dinv<<<(NN + 255) / 256, 256>>>();
    k_gemm1<<<gblocks, 256>>>(x, W1);
    k_scat1<<<(NE * 4 + 255) / 256, 256>>>(ei);
    k_layer2<<<(NN + 255) / 256, 256>>>(b1, W2);
    k_scat2<<<(NE * 2 + 255) / 256, 256>>>(ei);
    k_final<<<(NN + 255) / 256, 256>>>(b2, out);
}